// round 4
// baseline (speedup 1.0000x reference)
#include <cuda_runtime.h>
#include <math.h>

// Problem constants (fixed by the reference)
#define M_MOL   64
#define N_AT    24
#define P_DESC  276          // 24*23/2
#define T_ROWS  6000
#define NCHUNK  148          // one t-chunk per SM
#define CHUNK   41           // ceil(6000/148)

#define QCONST  0.22360679774997896f   // sqrt(5)/10
#define Q2      0.05f                  // q^2 = 5/sig^2 (exact)
#define CECONST 0.016666666666666666f  // 5/(3*sig^2)

typedef unsigned long long u64;

// Scratch (allocation-free rule: __device__ globals), 8B-aligned for b64 stores
__device__ __align__(16) float g_pG[NCHUNK * M_MOL * P_DESC];   // 10.45 MB partials
__device__ __align__(16) float g_pE[NCHUNK * M_MOL];

// ---------------------------------------------------------------------------
// helpers
// ---------------------------------------------------------------------------
__device__ __forceinline__ u64 pk(float lo, float hi) {
    u64 r; asm("mov.b64 %0, {%1,%2};" : "=l"(r) : "f"(lo), "f"(hi)); return r;
}
__device__ __forceinline__ float hadd(u64 v) {
    float a, b; asm("mov.b64 {%0,%1}, %2;" : "=f"(a), "=f"(b) : "l"(v)); return a + b;
}
__device__ __forceinline__ u64 ffma2(u64 a, u64 b, u64 c) {
    u64 d; asm("fma.rn.f32x2 %0, %1, %2, %3;" : "=l"(d) : "l"(a), "l"(b), "l"(c)); return d;
}
__device__ __forceinline__ u64 ldg2(const float* p) {
    u64 v; asm("ld.global.nc.b64 %0, [%1];" : "=l"(v) : "l"(p)); return v;
}
__device__ __forceinline__ u64 ldg2p(const float* p, int pred) {
    u64 v = 0;
    asm("{ .reg .pred q; setp.ne.s32 q, %2, 0; @q ld.global.nc.b64 %0, [%1]; }"
        : "+l"(v) : "l"(p), "r"(pred));
    return v;
}
__device__ __forceinline__ float wredf(float v) {
#pragma unroll
    for (int o = 16; o; o >>= 1) v += __shfl_xor_sync(0xffffffffu, v, o);
    return v;
}

// p -> (i, j), lower-triangular pair index (i>j), row-major tril order
__device__ __forceinline__ void pair_ij(int p, int& i, int& j) {
    float f = sqrtf(8.0f * (float)p + 1.0f);
    i = (int)((1.0f + f) * 0.5f);
    while (i * (i - 1) / 2 > p) --i;
    while ((i + 1) * i / 2 <= p) ++i;
    j = p - i * (i - 1) / 2;
}

__device__ __forceinline__ float invdist(const float* __restrict__ r, int p) {
    int i, j; pair_ij(p, i, j);
    float dx = r[i * 3 + 0] - r[j * 3 + 0];
    float dy = r[i * 3 + 1] - r[j * 3 + 1];
    float dz = r[i * 3 + 2] - r[j * 3 + 2];
    return rsqrtf(fmaf(dx, dx, fmaf(dy, dy, dz * dz)));
}

// ---------------------------------------------------------------------------
// Main contraction kernel. Grid: NCHUNK blocks (t-chunks) x 512 threads.
// Lane l owns descriptor pairs p = {64s+2l, 64s+2l+1}, s=0..3, plus tail
// slot s=4: p = {256+2l, 257+2l} for l<10. All p-dim math is packed f32x2.
// Warp w owns molecules 4w..4w+3 with q*xs and accumulators in registers.
// Per-t m-independent stats (||q xt||^2, q xt.jx) precomputed into shared.
// ---------------------------------------------------------------------------
__global__ __launch_bounds__(512) void k_main(const float* __restrict__ Rs,
                                              const float* __restrict__ xtr,
                                              const float* __restrict__ jxa) {
    __shared__ float sRs[M_MOL * N_AT * 3];
    __shared__ float sNt[CHUNK], sS2[CHUNK];
    const int tid = threadIdx.x;
    const int w = tid >> 5, l = tid & 31;
    const int c = blockIdx.x;
    const int t0 = c * CHUNK;
    const int ntl = min(CHUNK, T_ROWS - t0);   // may be <= 0 (empty last block)
    const int tailv = (l < 10);

    // stage Rs
    for (int i = tid; i < M_MOL * N_AT * 3; i += 512) sRs[i] = Rs[i];
    __syncthreads();

    // per-warp xq (= q * xs) and nq = ||xq||^2 for this warp's 4 molecules
    u64 xq[4][5];
    float nq[4];
#pragma unroll
    for (int mm = 0; mm < 4; mm++) {
        const float* rb = sRs + (w * 4 + mm) * N_AT * 3;
        float sq = 0.0f;
#pragma unroll
        for (int s = 0; s < 5; s++) {
            int p0 = (s < 4) ? s * 64 + 2 * l : 256 + 2 * l;
            float x0 = 0.0f, x1 = 0.0f;
            if (s < 4 || tailv) {
                x0 = QCONST * invdist(rb, p0);
                x1 = QCONST * invdist(rb, p0 + 1);
            }
            xq[mm][s] = pk(x0, x1);
            sq = fmaf(x0, x0, fmaf(x1, x1, sq));
        }
        nq[mm] = wredf(sq);
    }

    // pre-phase: per-t stats shared by all warps of this block
    for (int k = w; k < ntl; k += 16) {
        const float* xr = xtr + (size_t)(t0 + k) * P_DESC + 2 * l;
        const float* jr = jxa + (size_t)(t0 + k) * P_DESC + 2 * l;
        u64 a = 0, b = 0;
#pragma unroll
        for (int s = 0; s < 4; s++) {
            u64 xv = ldg2(xr + 64 * s);
            u64 jv = ldg2(jr + 64 * s);
            a = ffma2(xv, xv, a);
            b = ffma2(xv, jv, b);
        }
        {
            u64 xv = ldg2p(xr + 256, tailv);
            u64 jv = ldg2p(jr + 256, tailv);
            a = ffma2(xv, xv, a);
            b = ffma2(xv, jv, b);
        }
        float av = wredf(hadd(a));
        float bv = wredf(hadd(b));
        if (l == 0) { sNt[k] = Q2 * av; sS2[k] = QCONST * bv; }
    }
    __syncthreads();

    // accumulators
    u64 acc[4][5];
    float S1[4], eac[4];
#pragma unroll
    for (int mm = 0; mm < 4; mm++) {
        S1[mm] = 0.0f; eac[mm] = 0.0f;
#pragma unroll
        for (int s = 0; s < 5; s++) acc[mm][s] = 0;
    }

    const float* xr = xtr + (size_t)t0 * P_DESC + 2 * l;
    const float* jr = jxa + (size_t)t0 * P_DESC + 2 * l;
    for (int k = 0; k < ntl; k++, xr += P_DESC, jr += P_DESC) {
        u64 xt[5], jx[5];
#pragma unroll
        for (int s = 0; s < 4; s++) { xt[s] = ldg2(xr + 64 * s); jx[s] = ldg2(jr + 64 * s); }
        xt[4] = ldg2p(xr + 256, tailv);
        jx[4] = ldg2p(jr + 256, tailv);
        const float ntv = sNt[k], s2v = sS2[k];

        // phase A: packed partial cross/dot per molecule
        float cs[4], ds[4];
#pragma unroll
        for (int mm = 0; mm < 4; mm++) {
            u64 cp = 0, dp = 0;
#pragma unroll
            for (int s = 0; s < 5; s++) {
                cp = ffma2(xq[mm][s], xt[s], cp);
                dp = ffma2(xq[mm][s], jx[s], dp);
            }
            cs[mm] = hadd(cp);
            ds[mm] = hadd(dp);
        }
        // phase B: interleaved butterfly over 8 values (hides SHFL latency)
#pragma unroll
        for (int o = 16; o; o >>= 1) {
#pragma unroll
            for (int mm = 0; mm < 4; mm++) {
                cs[mm] += __shfl_xor_sync(0xffffffffu, cs[mm], o);
                ds[mm] += __shfl_xor_sync(0xffffffffu, ds[mm], o);
            }
        }
        // phase C: scalar chain + packed accumulator update
#pragma unroll
        for (int mm = 0; mm < 4; mm++) {
            float dotm = ds[mm] - s2v;
            float d2 = nq[mm] + ntv - 2.0f * QCONST * cs[mm];
            d2 = fmaxf(d2, 1e-12f);
            float d  = d2 * rsqrtf(d2);
            float a  = CECONST * __expf(-d);
            float c1 = a * dotm;
            float c2 = fmaf(a, d, a);
            eac[mm]  = fmaf(c2, dotm, eac[mm]);
            S1[mm]  += c1;
            float nc1s = -QCONST * c1;
            u64 nc1 = pk(nc1s, nc1s);
            u64 nc2 = pk(-c2, -c2);
#pragma unroll
            for (int s = 0; s < 5; s++) {
                acc[mm][s] = ffma2(nc1, xt[s], acc[mm][s]);
                acc[mm][s] = ffma2(nc2, jx[s], acc[mm][s]);
            }
        }
    }

    // epilogue: G = xq*S1 + acc, packed b64 stores
#pragma unroll
    for (int mm = 0; mm < 4; mm++) {
        float* dst = g_pG + ((size_t)c * M_MOL + w * 4 + mm) * P_DESC;
        u64 s1p = pk(S1[mm], S1[mm]);
#pragma unroll
        for (int s = 0; s < 5; s++) {
            u64 g = ffma2(s1p, xq[mm][s], acc[mm][s]);
            int p0 = (s < 4) ? s * 64 + 2 * l : 256 + 2 * l;
            if (s < 4 || tailv) *reinterpret_cast<u64*>(dst + p0) = g;
        }
        if (l == 0) g_pE[c * M_MOL + w * 4 + mm] = eac[mm];
    }
}

// ---------------------------------------------------------------------------
// Finalize: reduce partials (3-way chunk-parallel, MLP-deep), apply xs^3,
// scatter pair forces, write Es + Fs.
// Output: d_out[0:64] = Es, d_out[64:4672] = Fs[m][atom][xyz]
// ---------------------------------------------------------------------------
__global__ void k_fin(const float* __restrict__ Rs, float* __restrict__ out) {
    const int m = blockIdx.x, tid = threadIdx.x;
    __shared__ float part[3][P_DESC];
    __shared__ float fpair[P_DESC];
    __shared__ float rs[N_AT * 3];
    __shared__ float ep[NCHUNK];
    const int g = tid / 288, p = tid - g * 288;

    if (tid < N_AT * 3) rs[tid] = Rs[m * N_AT * 3 + tid];
    if (tid < NCHUNK)   ep[tid] = g_pE[tid * M_MOL + m];

    if (p < P_DESC) {
        float a0 = 0, a1 = 0, a2 = 0, a3 = 0;
        const float* src = g_pG + (size_t)m * P_DESC + p;
        const size_t stride = (size_t)M_MOL * P_DESC;
        int c = g;
        for (; c + 9 < NCHUNK; c += 12) {
            a0 += src[(size_t)c * stride];
            a1 += src[(size_t)(c + 3) * stride];
            a2 += src[(size_t)(c + 6) * stride];
            a3 += src[(size_t)(c + 9) * stride];
        }
        for (; c < NCHUNK; c += 3) a0 += src[(size_t)c * stride];
        part[g][p] = (a0 + a1) + (a2 + a3);
    }
    __syncthreads();

    if (tid < P_DESC) {
        float inv = invdist(rs, tid);
        float gsum = part[0][tid] + part[1][tid] + part[2][tid];
        fpair[tid] = gsum * inv * inv * inv;       // Fs_x
    }
    if (tid == 0) {
        float e = 0.0f;
        for (int c = 0; c < NCHUNK; c++) e += ep[c];
        out[m] = e / QCONST;                       // * STD(=1) + C(=0)
    }
    __syncthreads();

    if (tid < N_AT * 3) {
        const int b = tid / 3, kk = tid - b * 3;
        const float rb = rs[b * 3 + kk];
        float fb = 0.0f;
#pragma unroll
        for (int a = 0; a < N_AT; a++) {
            if (a == b) continue;
            const int i = a > b ? a : b;
            const int j = a > b ? b : a;
            fb += (rs[a * 3 + kk] - rb) * fpair[i * (i - 1) / 2 + j];
        }
        out[M_MOL + m * N_AT * 3 + tid] = fb;
    }
}

// ---------------------------------------------------------------------------
extern "C" void kernel_launch(void* const* d_in, const int* in_sizes, int n_in,
                              void* d_out, int out_size) {
    const float* Rs  = (const float*)d_in[0];   // [64, 24, 3]
    const float* xtr = (const float*)d_in[1];   // [6000, 276]
    const float* jxa = (const float*)d_in[2];   // [6000, 276]
    float* out = (float*)d_out;                 // [4672] f32

    k_main<<<NCHUNK, 512>>>(Rs, xtr, jxa);
    k_fin<<<M_MOL, 864>>>(Rs, out);
}

// round 10
// speedup vs baseline: 1.2255x; 1.2255x over previous
#include <cuda_runtime.h>
#include <math.h>

// Problem constants (fixed by the reference)
#define M_MOL   64
#define N_AT    24
#define P_DESC  276          // 24*23/2
#define T_ROWS  6000
#define MG      2            // molecule groups (32 each)
#define TC      74           // t-chunks
#define CHUNK   82           // ceil(6000/74)

#define QCONST  0.22360679774997896f   // sqrt(5)/10
#define Q2      0.05f                  // q^2 = 5/sig^2 (exact)
#define CECONST 0.016666666666666666f  // 5/(3*sig^2)

typedef unsigned long long u64;

// Scratch (allocation-free rule: __device__ globals), 8B-aligned
__device__ __align__(16) float g_pG[TC * M_MOL * P_DESC];   // 5.23 MB partials
__device__ __align__(16) float g_pE[TC * M_MOL];

// ---------------------------------------------------------------------------
// helpers
// ---------------------------------------------------------------------------
__device__ __forceinline__ u64 pk(float lo, float hi) {
    u64 r; asm("mov.b64 %0, {%1,%2};" : "=l"(r) : "f"(lo), "f"(hi)); return r;
}
__device__ __forceinline__ float hadd(u64 v) {
    float a, b; asm("mov.b64 {%0,%1}, %2;" : "=f"(a), "=f"(b) : "l"(v)); return a + b;
}
__device__ __forceinline__ u64 ffma2(u64 a, u64 b, u64 c) {
    u64 d; asm("fma.rn.f32x2 %0, %1, %2, %3;" : "=l"(d) : "l"(a), "l"(b), "l"(c)); return d;
}
__device__ __forceinline__ u64 ldg2(const float* p) {
    u64 v; asm("ld.global.nc.b64 %0, [%1];" : "=l"(v) : "l"(p)); return v;
}
__device__ __forceinline__ u64 ldg2p(const float* p, int pred) {
    u64 v = 0;
    asm("{ .reg .pred q; setp.ne.s32 q, %2, 0; @q ld.global.nc.b64 %0, [%1]; }"
        : "+l"(v) : "l"(p), "r"(pred));
    return v;
}
__device__ __forceinline__ float wredf(float v) {
#pragma unroll
    for (int o = 16; o; o >>= 1) v += __shfl_xor_sync(0xffffffffu, v, o);
    return v;
}

// p -> (i, j), lower-triangular pair index (i>j), row-major tril order
__device__ __forceinline__ void pair_ij(int p, int& i, int& j) {
    float f = sqrtf(8.0f * (float)p + 1.0f);
    i = (int)((1.0f + f) * 0.5f);
    while (i * (i - 1) / 2 > p) --i;
    while ((i + 1) * i / 2 <= p) ++i;
    j = p - i * (i - 1) / 2;
}

__device__ __forceinline__ float invdist(const float* __restrict__ r, int p) {
    int i, j; pair_ij(p, i, j);
    float dx = r[i * 3 + 0] - r[j * 3 + 0];
    float dy = r[i * 3 + 1] - r[j * 3 + 1];
    float dz = r[i * 3 + 2] - r[j * 3 + 2];
    return rsqrtf(fmaf(dx, dx, fmaf(dy, dy, dz * dz)));
}

// ---------------------------------------------------------------------------
// Main contraction. Grid: 148 blocks = MG(2) molecule-groups x TC(74) t-chunks,
// 512 threads (16 warps). Warp w owns 2 molecules m = mg*32 + 2w + {0,1}.
// Lane l owns descriptor pairs p = {64s+2l, 64s+2l+1}, s=0..3, plus tail slot
// s=4: p = {256+2l} for l<10. All p-dim math is packed fma.rn.f32x2.
// Per-t m-independent stats (q^2||xt||^2, q xt.jx) precomputed into shared.
// Register budget ~90/thread -> no spills at 512 threads.
// ---------------------------------------------------------------------------
__global__ __launch_bounds__(512) void k_main(const float* __restrict__ Rs,
                                              const float* __restrict__ xtr,
                                              const float* __restrict__ jxa) {
    __shared__ float sRs[32 * N_AT * 3];
    __shared__ float sNt[CHUNK], sS2[CHUNK];
    const int tid = threadIdx.x;
    const int w = tid >> 5, l = tid & 31;
    const int mg = blockIdx.x / TC;
    const int tc = blockIdx.x - mg * TC;
    const int t0 = tc * CHUNK;
    const int ntl = min(CHUNK, T_ROWS - t0);
    const int tailv = (l < 10);

    // stage this group's 32 molecules of Rs
    for (int i = tid; i < 32 * N_AT * 3; i += 512)
        sRs[i] = Rs[mg * 32 * N_AT * 3 + i];
    __syncthreads();

    // per-warp xq (= q * xs) and nq = ||xq||^2 for this warp's 2 molecules
    u64 xq[2][5];
    float nq[2];
#pragma unroll
    for (int mm = 0; mm < 2; mm++) {
        const float* rb = sRs + (w * 2 + mm) * N_AT * 3;
        float sq = 0.0f;
#pragma unroll
        for (int s = 0; s < 5; s++) {
            int p0 = (s < 4) ? s * 64 + 2 * l : 256 + 2 * l;
            float x0 = 0.0f, x1 = 0.0f;
            if (s < 4 || tailv) {
                x0 = QCONST * invdist(rb, p0);
                x1 = QCONST * invdist(rb, p0 + 1);
            }
            xq[mm][s] = pk(x0, x1);
            sq = fmaf(x0, x0, fmaf(x1, x1, sq));
        }
        nq[mm] = wredf(sq);
    }

    // pre-phase: per-t stats shared by all warps of this block
    for (int k = w; k < ntl; k += 16) {
        const float* xr = xtr + (size_t)(t0 + k) * P_DESC + 2 * l;
        const float* jr = jxa + (size_t)(t0 + k) * P_DESC + 2 * l;
        u64 a = 0, b = 0;
#pragma unroll
        for (int s = 0; s < 4; s++) {
            u64 xv = ldg2(xr + 64 * s);
            u64 jv = ldg2(jr + 64 * s);
            a = ffma2(xv, xv, a);
            b = ffma2(xv, jv, b);
        }
        {
            u64 xv = ldg2p(xr + 256, tailv);
            u64 jv = ldg2p(jr + 256, tailv);
            a = ffma2(xv, xv, a);
            b = ffma2(xv, jv, b);
        }
        float av = wredf(hadd(a));
        float bv = wredf(hadd(b));
        if (l == 0) { sNt[k] = Q2 * av; sS2[k] = QCONST * bv; }
    }
    __syncthreads();

    // accumulators
    u64 acc[2][5];
    float S1[2], eac[2];
#pragma unroll
    for (int mm = 0; mm < 2; mm++) {
        S1[mm] = 0.0f; eac[mm] = 0.0f;
#pragma unroll
        for (int s = 0; s < 5; s++) acc[mm][s] = 0;
    }

    const float* xr = xtr + (size_t)t0 * P_DESC + 2 * l;
    const float* jr = jxa + (size_t)t0 * P_DESC + 2 * l;
    for (int k = 0; k < ntl; k++, xr += P_DESC, jr += P_DESC) {
        u64 xt[5], jx[5];
#pragma unroll
        for (int s = 0; s < 4; s++) { xt[s] = ldg2(xr + 64 * s); jx[s] = ldg2(jr + 64 * s); }
        xt[4] = ldg2p(xr + 256, tailv);
        jx[4] = ldg2p(jr + 256, tailv);
        const float ntv = sNt[k], s2v = sS2[k];

        // phase A: packed partial cross/dot per molecule
        float cs[2], ds[2];
#pragma unroll
        for (int mm = 0; mm < 2; mm++) {
            u64 cp = 0, dp = 0;
#pragma unroll
            for (int s = 0; s < 5; s++) {
                cp = ffma2(xq[mm][s], xt[s], cp);
                dp = ffma2(xq[mm][s], jx[s], dp);
            }
            cs[mm] = hadd(cp);
            ds[mm] = hadd(dp);
        }
        // phase B: interleaved butterfly over 4 values (hides SHFL latency)
#pragma unroll
        for (int o = 16; o; o >>= 1) {
#pragma unroll
            for (int mm = 0; mm < 2; mm++) {
                cs[mm] += __shfl_xor_sync(0xffffffffu, cs[mm], o);
                ds[mm] += __shfl_xor_sync(0xffffffffu, ds[mm], o);
            }
        }
        // phase C: scalar chain + packed accumulator update
#pragma unroll
        for (int mm = 0; mm < 2; mm++) {
            float dotm = ds[mm] - s2v;
            float d2 = fmaf(-2.0f * QCONST, cs[mm], nq[mm] + ntv);
            d2 = fmaxf(d2, 1e-12f);
            float d  = d2 * rsqrtf(d2);
            float a  = CECONST * __expf(-d);
            float c1 = a * dotm;
            float c2 = fmaf(a, d, a);
            eac[mm]  = fmaf(c2, dotm, eac[mm]);
            S1[mm]  += c1;
            float nc1s = -QCONST * c1;
            u64 nc1 = pk(nc1s, nc1s);
            u64 nc2 = pk(-c2, -c2);
#pragma unroll
            for (int s = 0; s < 5; s++) {
                acc[mm][s] = ffma2(nc1, xt[s], acc[mm][s]);
                acc[mm][s] = ffma2(nc2, jx[s], acc[mm][s]);
            }
        }
    }

    // epilogue: G = xq*S1 + acc, packed b64 stores
#pragma unroll
    for (int mm = 0; mm < 2; mm++) {
        const int m = mg * 32 + w * 2 + mm;
        float* dst = g_pG + ((size_t)tc * M_MOL + m) * P_DESC;
        u64 s1p = pk(S1[mm], S1[mm]);
#pragma unroll
        for (int s = 0; s < 5; s++) {
            u64 g = ffma2(s1p, xq[mm][s], acc[mm][s]);
            int p0 = (s < 4) ? s * 64 + 2 * l : 256 + 2 * l;
            if (s < 4 || tailv) *reinterpret_cast<u64*>(dst + p0) = g;
        }
        if (l == 0) g_pE[tc * M_MOL + m] = eac[mm];
    }
}

// ---------------------------------------------------------------------------
// Finalize: reduce partials (3 chunk-parallel groups of 288 threads, 4
// accumulators each for MLP), apply xs^3, scatter pair forces, write Es + Fs.
// 864 threads/block (must stay <= 1024!).
// Output: d_out[0:64] = Es, d_out[64:4672] = Fs[m][atom][xyz]
// ---------------------------------------------------------------------------
__global__ void k_fin(const float* __restrict__ Rs, float* __restrict__ out) {
    const int m = blockIdx.x, tid = threadIdx.x;
    __shared__ float part[3][P_DESC];
    __shared__ float fpair[P_DESC];
    __shared__ float rs[N_AT * 3];
    __shared__ float ep[TC];
    const int g = tid / 288, p = tid - g * 288;

    if (tid < N_AT * 3) rs[tid] = Rs[m * N_AT * 3 + tid];
    if (tid < TC)       ep[tid] = g_pE[tid * M_MOL + m];

    if (p < P_DESC) {
        float a0 = 0.0f, a1 = 0.0f, a2 = 0.0f, a3 = 0.0f;
        const float* src = g_pG + (size_t)m * P_DESC + p;
        const size_t stride = (size_t)M_MOL * P_DESC;
        int c = g;
        for (; c + 9 < TC; c += 12) {
            a0 += src[(size_t)c * stride];
            a1 += src[(size_t)(c + 3) * stride];
            a2 += src[(size_t)(c + 6) * stride];
            a3 += src[(size_t)(c + 9) * stride];
        }
        for (; c < TC; c += 3) a0 += src[(size_t)c * stride];
        part[g][p] = (a0 + a1) + (a2 + a3);
    }
    __syncthreads();

    if (tid < P_DESC) {
        float inv = invdist(rs, tid);
        float gsum = part[0][tid] + part[1][tid] + part[2][tid];
        fpair[tid] = gsum * inv * inv * inv;       // Fs_x
    }
    if (tid == 0) {
        float e = 0.0f;
        for (int c = 0; c < TC; c++) e += ep[c];
        out[m] = e / QCONST;                       // * STD(=1) + C(=0)
    }
    __syncthreads();

    if (tid < N_AT * 3) {
        const int b = tid / 3, kk = tid - b * 3;
        const float rb = rs[b * 3 + kk];
        float fb = 0.0f;
#pragma unroll
        for (int a = 0; a < N_AT; a++) {
            if (a == b) continue;
            const int i = a > b ? a : b;
            const int j = a > b ? b : a;
            fb += (rs[a * 3 + kk] - rb) * fpair[i * (i - 1) / 2 + j];
        }
        out[M_MOL + m * N_AT * 3 + tid] = fb;
    }
}

// ---------------------------------------------------------------------------
extern "C" void kernel_launch(void* const* d_in, const int* in_sizes, int n_in,
                              void* d_out, int out_size) {
    const float* Rs  = (const float*)d_in[0];   // [64, 24, 3]
    const float* xtr = (const float*)d_in[1];   // [6000, 276]
    const float* jxa = (const float*)d_in[2];   // [6000, 276]
    float* out = (float*)d_out;                 // [4672] f32

    k_main<<<MG * TC, 512>>>(Rs, xtr, jxa);
    k_fin<<<M_MOL, 864>>>(Rs, out);
}